// round 16
// baseline (speedup 1.0000x reference)
#include <cuda_runtime.h>
#include <cuda_bf16.h>
#include <cstdint>
#include <cstddef>

// ============================================================================
// out[16384,2048] = (x @ W^T) * (1/sqrt(2048)) + 0.1*b
// tcgen05 path (sm_103a): x = hi + lo (bf16 split), 64-iteration loop:
//   it  0..31 : bf16  hi_x * hi_w              (KC=64)
//   it 32..47 : e4m3 (hi_x*2^-4) * (lo_w*2^4)  (KC=128) = hi_x*lo_w
//   it 48..63 : e4m3 (lo_x*2^4) * (hi_w*2^-4)           = lo_x*hi_w
// R15: ONE fused kernel. bids 0..143 = converter CTAs (fp32 -> scratch tiles,
// K-superchunk-major, publish flags); bids 144..655 = exact R11 GEMM CTAs
// (256x256 tile, 3-stage bulk pipeline, warp-specialized control) whose
// producer spin-waits each superchunk's flags once. Conversion (~45us) runs
// CONCURRENTLY with the GEMM instead of serially before it.
// cg2/multicast abandoned (R6/R13/R14: structural cost > traffic win).
// Fallback path (plain sm_103 pass): SIMT fp32 GEMM, same launch config.
// ============================================================================

#if defined(__CUDA_ARCH_FEAT_SM103_ALL) || defined(__CUDA_ARCH_FEAT_SM100_ALL) \
 || defined(__CUDA_ARCH_FEAT_SM101_ALL) \
 || (defined(__CUDA_ARCH_SPECIFIC__) && (__CUDA_ARCH_SPECIFIC__ >= 1000)) \
 || (defined(__CUDA_ARCH_FAMILY_SPECIFIC__) && (__CUDA_ARCH_FAMILY_SPECIFIC__ >= 1000))
#define HAS_TCGEN05 1
#else
#define HAS_TCGEN05 0
#endif

#define N_ROWS 16384
#define D_IN   2048
#define D_OUT  2048

#define TMSUB 128
#define TM    256
#define TN    256
#define NITER 64                    // 32 bf16 + 16 fp8 + 16 fp8
#define NSTAGE 3
#define NCONV 144                   // converter CTAs (all inside wave 1)

#define A_UNIT 16384                // 128 rows x 128B
#define B_UNIT 32768                // 256 rows x 128B
#define STAGE_BYTES (2 * A_UNIT + B_UNIT)   // 65536
#define SMEM_TMEMPTR 0
#define SMEM_BAR     64             // FULL +0,8,16 | CB +24,32,40 | FINAL +48
#define SMEM_STAGE0  1024
#define SMEM_TOTAL   (SMEM_STAGE0 + NSTAGE * STAGE_BYTES)  // 197632

#define TMEM_COLS 512

// idesc: [4:6) c=F32=1, [7:10) a_fmt, [10:13) b_fmt, [17:23) N>>3, [24:29) M>>4
#define MMA_IDESC_F16 ((1u << 4) | (1u << 7) | (1u << 10) | (32u << 17) | (8u << 24))
#define MMA_IDESC_F8  ((1u << 4) | (0u << 7) | (0u << 10) | (32u << 17) | (8u << 24))

#define SHI 0.0625f
#define SLO 16.0f

// ---------------- scratch + flags (device globals: allocation-free) --------
// per row-tile: units 0..31 bf16-hi (2 per superchunk), 32..47 hi8, 48..63 lo8
__device__ __align__(128) unsigned char g_X[(size_t)(N_ROWS / TMSUB) * 64 * A_UNIT]; // 128 MB
__device__ __align__(128) unsigned char g_W[(size_t)(D_OUT / TN)    * 64 * B_UNIT];  // 16 MB
// g_flags[0..15] = wdone[tk] (target 8), g_flags[16..31] = xdone[tk] (target 128)
__device__ int g_flags[32];

// ---------------- portable helpers ----------------
__device__ __forceinline__ uint32_t smem_u32(const void* p) {
    uint32_t a;
    asm("{ .reg .u64 t; cvta.to.shared.u64 t, %1; cvt.u32.u64 %0, t; }" : "=r"(a) : "l"(p));
    return a;
}

__device__ __forceinline__ void mbar_init(uint32_t mbar, uint32_t count) {
    asm volatile("mbarrier.init.shared.b64 [%0], %1;" :: "r"(mbar), "r"(count) : "memory");
}

__device__ __forceinline__ void mbar_expect_tx(uint32_t mbar, uint32_t bytes) {
    asm volatile("mbarrier.arrive.expect_tx.shared.b64 _, [%0], %1;"
                 :: "r"(mbar), "r"(bytes) : "memory");
}

__device__ __forceinline__ void mbar_wait(uint32_t mbar, uint32_t parity) {
    asm volatile(
        "{\n\t"
        ".reg .pred P;\n\t"
        "WAIT_%=:\n\t"
        "mbarrier.try_wait.parity.acquire.cta.shared::cta.b64 P, [%0], %1, 0x989680;\n\t"
        "@!P bra WAIT_%=;\n\t"
        "}\n"
        :: "r"(mbar), "r"(parity) : "memory");
}

__device__ __forceinline__ void bulk_g2s(uint32_t dst_smem, const void* src_gmem,
                                         uint32_t bytes, uint32_t mbar) {
    asm volatile(
        "cp.async.bulk.shared::cluster.global.mbarrier::complete_tx::bytes [%0], [%1], %2, [%3];"
        :: "r"(dst_smem), "l"(src_gmem), "r"(bytes), "r"(mbar) : "memory");
}

__device__ __forceinline__ uint64_t make_desc(uint32_t smem_addr) {
    const uint64_t BASE = (uint64_t(2) << 61)
                        | (uint64_t(1) << 46)
                        | (uint64_t(64) << 32)
                        | (uint64_t(1) << 16);
    return BASE | ((uint64_t)(smem_addr >> 4) & 0x3FFF);
}

__device__ __forceinline__ uint16_t f2_e4m3x2(float hi, float lo) {
    uint16_t r;
    asm("cvt.rn.satfinite.e4m3x2.f32 %0, %1, %2;" : "=h"(r) : "f"(hi), "f"(lo));
    return r;
}

__device__ __forceinline__ int ld_acq(const int* p) {
    int v;
    asm volatile("ld.acquire.gpu.global.b32 %0, [%1];" : "=r"(v) : "l"(p) : "memory");
    return v;
}

__device__ __forceinline__ void red_release(int* p, int v) {
    asm volatile("red.release.gpu.global.add.s32 [%0], %1;" :: "l"(p), "r"(v) : "memory");
}

#if HAS_TCGEN05
// ---------------- 'a'-pass only wrappers ----------------
__device__ __forceinline__ void mma_f16_ss(uint32_t d_tmem, uint64_t a_desc, uint64_t b_desc,
                                           uint32_t en) {
    asm volatile(
        "{\n\t"
        ".reg .pred p;\n\t"
        "setp.ne.u32 p, %5, 0;\n\t"
        "tcgen05.mma.cta_group::1.kind::f16 [%0], %1, %2, %3, {%4, %4, %4, %4}, p;\n\t"
        "}"
        :: "r"(d_tmem), "l"(a_desc), "l"(b_desc), "r"(MMA_IDESC_F16), "r"(0u), "r"(en)
        : "memory");
}

__device__ __forceinline__ void mma_f8_ss(uint32_t d_tmem, uint64_t a_desc, uint64_t b_desc,
                                          uint32_t en) {
    asm volatile(
        "{\n\t"
        ".reg .pred p;\n\t"
        "setp.ne.u32 p, %5, 0;\n\t"
        "tcgen05.mma.cta_group::1.kind::f8f6f4 [%0], %1, %2, %3, {%4, %4, %4, %4}, p;\n\t"
        "}"
        :: "r"(d_tmem), "l"(a_desc), "l"(b_desc), "r"(MMA_IDESC_F8), "r"(0u), "r"(en)
        : "memory");
}

__device__ __forceinline__ void tcommit(uint32_t mbar) {
    asm volatile("tcgen05.commit.cta_group::1.mbarrier::arrive::one.shared::cluster.b64 [%0];"
                 :: "r"(mbar) : "memory");
}

#define TLD_32X32B_X32(r, tmem_addr) \
    asm volatile( \
        "tcgen05.ld.sync.aligned.32x32b.x32.b32 " \
        "{%0, %1, %2, %3, %4, %5, %6, %7, " \
        " %8, %9, %10, %11, %12, %13, %14, %15, " \
        " %16, %17, %18, %19, %20, %21, %22, %23, " \
        " %24, %25, %26, %27, %28, %29, %30, %31}, [%32];" \
        : "=r"((r)[0]),  "=r"((r)[1]),  "=r"((r)[2]),  "=r"((r)[3]), \
          "=r"((r)[4]),  "=r"((r)[5]),  "=r"((r)[6]),  "=r"((r)[7]), \
          "=r"((r)[8]),  "=r"((r)[9]),  "=r"((r)[10]), "=r"((r)[11]), \
          "=r"((r)[12]), "=r"((r)[13]), "=r"((r)[14]), "=r"((r)[15]), \
          "=r"((r)[16]), "=r"((r)[17]), "=r"((r)[18]), "=r"((r)[19]), \
          "=r"((r)[20]), "=r"((r)[21]), "=r"((r)[22]), "=r"((r)[23]), \
          "=r"((r)[24]), "=r"((r)[25]), "=r"((r)[26]), "=r"((r)[27]), \
          "=r"((r)[28]), "=r"((r)[29]), "=r"((r)[30]), "=r"((r)[31]) \
        : "r"(tmem_addr))
#endif  // HAS_TCGEN05

// ============================================================================
// One conversion item: (tile_rows TILE_R, superchunk tk, row-tile tr) of src
// fp32 -> bf16-hi (2 units) + hi8 + lo8, SW128 swizzled. 128 threads.
// ============================================================================
__device__ void convert_item(const float* __restrict__ src, unsigned char* dstBase,
                             int TILE_R, int tk, int tr) {
    const size_t tile = (size_t)TILE_R * 128;
    unsigned char* base = dstBase + (size_t)tr * (64 * tile);
    unsigned char* hiB16a = base + (size_t)(2 * tk)     * tile;
    unsigned char* hiB16b = base + (size_t)(2 * tk + 1) * tile;
    unsigned char* hi8    = base + (size_t)(32 + tk)    * tile;
    unsigned char* lo8    = base + (size_t)(48 + tk)    * tile;

    const int quads = TILE_R * 32;
    for (int t = threadIdx.x; t < quads; t += 128) {
        const int r = t >> 5;
        const int q = t & 31;
        const float4 v = *(const float4*)(src + (size_t)(tr * TILE_R + r) * D_IN + tk * 128 + q * 4);

        const __nv_bfloat16 h0 = __float2bfloat16(v.x);
        const __nv_bfloat16 h1 = __float2bfloat16(v.y);
        const __nv_bfloat16 h2 = __float2bfloat16(v.z);
        const __nv_bfloat16 h3 = __float2bfloat16(v.w);
        const float f0 = __bfloat162float(h0), f1 = __bfloat162float(h1);
        const float f2 = __bfloat162float(h2), f3 = __bfloat162float(h3);
        const float l0 = v.x - f0, l1 = v.y - f1, l2 = v.z - f2, l3 = v.w - f3;

        const uint32_t offB = (uint32_t)r * 128u + (uint32_t)((q * 4) & 63) * 2u;
        const uint32_t swB = offB ^ ((offB >> 3) & 0x70);
        unsigned char* bt = (q < 16) ? hiB16a : hiB16b;
        uint2 hp;
        hp.x = ((uint32_t)__bfloat16_as_ushort(h1) << 16) | __bfloat16_as_ushort(h0);
        hp.y = ((uint32_t)__bfloat16_as_ushort(h3) << 16) | __bfloat16_as_ushort(h2);
        *(uint2*)(bt + swB) = hp;

        const uint32_t off8 = (uint32_t)r * 128u + (uint32_t)q * 4u;
        const uint32_t sw8 = off8 ^ ((off8 >> 3) & 0x70);
        const uint32_t wHi = (uint32_t)f2_e4m3x2(f1 * SHI, f0 * SHI)
                           | ((uint32_t)f2_e4m3x2(f3 * SHI, f2 * SHI) << 16);
        const uint32_t wLo = (uint32_t)f2_e4m3x2(l1 * SLO, l0 * SLO)
                           | ((uint32_t)f2_e4m3x2(l3 * SLO, l2 * SLO) << 16);
        *(uint32_t*)(hi8 + sw8) = wHi;
        *(uint32_t*)(lo8 + sw8) = wLo;
    }
}

// iteration -> B tile unit (A unit is just `it`)
__device__ __forceinline__ int b_unit(int j) {
    return j < 32 ? j : (j < 48 ? j + 16 : j - 16);
}
// iteration -> source superchunk (same for A and B sides)
__device__ __forceinline__ int tk_of(int j) {
    return j < 32 ? (j >> 1) : (j < 48 ? j - 32 : j - 48);
}

// ============================================================================
// Fused kernel: grid 656 x 128 threads.
//   bid 0..143   converter (W items first, then X items, superchunk-major)
//   bid 144..655 GEMM: g = bid-144, tn = g&7, tm = g>>3 (exact R11 body)
// ============================================================================
__global__ void __launch_bounds__(128, 1) fused_kernel(const float* __restrict__ x,
                                                       const float* __restrict__ w,
                                                       const float* __restrict__ bias,
                                                       float* __restrict__ out) {
    const int bid = blockIdx.x;
#if HAS_TCGEN05
    if (bid < NCONV) {
        // ---------------- CONVERTER ----------------
        // W: 128 items (tk 0..15 x 8 tn-tiles), target wdone[tk]=8
        for (int i = bid; i < 16 * 8; i += NCONV) {
            const int tk = i >> 3, tr = i & 7;
            convert_item(w, g_W, TN, tk, tr);
            __syncthreads();
            __threadfence();
            if (threadIdx.x == 0) red_release(&g_flags[tk], 1);
        }
        // X: 2048 items (tk 0..15 x 128 row-tiles), target xdone[tk]=128
        for (int i = bid; i < 16 * 128; i += NCONV) {
            const int tk = i >> 7, tr = i & 127;
            convert_item(x, g_X, TMSUB, tk, tr);
            __syncthreads();
            __threadfence();
            if (threadIdx.x == 0) red_release(&g_flags[16 + tk], 1);
        }
        return;
    }

    // ---------------- GEMM (exact R11 body) ----------------
    extern __shared__ __align__(1024) unsigned char smem[];
    const uint32_t sb = smem_u32(smem);
    const int tid = threadIdx.x;
    const int wid = tid >> 5, lid = tid & 31;
    const int g = bid - NCONV;
    const int tn = g & 7;     // 0..7
    const int tm = g >> 3;    // 0..63

    const uint32_t FULL  = sb + SMEM_BAR + 0;
    const uint32_t CB    = sb + SMEM_BAR + 24;
    const uint32_t FINAL = sb + SMEM_BAR + 48;

    if (tid == 0) {
        #pragma unroll
        for (int i = 0; i < NSTAGE; i++) { mbar_init(FULL + i * 8, 1); mbar_init(CB + i * 8, 1); }
        mbar_init(FINAL, 1);
        asm volatile("fence.proxy.async.shared::cta;" ::: "memory");
    }
    if (wid == 0) {
        asm volatile("tcgen05.alloc.cta_group::1.sync.aligned.shared::cta.b32 [%0], %1;"
                     :: "r"(sb + SMEM_TMEMPTR), "r"(TMEM_COLS) : "memory");
    }
    __syncthreads();
    uint32_t tmem;
    asm volatile("ld.shared.b32 %0, [%1];" : "=r"(tmem) : "r"(sb + SMEM_TMEMPTR));
    if (wid == 0)
        asm volatile("tcgen05.relinquish_alloc_permit.cta_group::1.sync.aligned;");
    __syncthreads();

    if (tid == 0) {
        // ---------------- PRODUCER (flag-gated ring refill) ----------------
        const unsigned char* a0Src = g_X + (size_t)(tm * 2 + 0) * 64 * A_UNIT;
        const unsigned char* a1Src = g_X + (size_t)(tm * 2 + 1) * 64 * A_UNIT;
        const unsigned char* bSrc  = g_W + (size_t)tn * 64 * B_UNIT;

        int cbPh[NSTAGE] = {0, 0, 0};
        int doneTk = -1;   // max superchunk confirmed converted
        for (int j = 0; j < NITER; j++) {
            const int s = j % NSTAGE;
            const int tk = tk_of(j);
            if (tk > doneTk) {
                while (ld_acq(&g_flags[tk]) < 8 || ld_acq(&g_flags[16 + tk]) < 128)
                    __nanosleep(128);
                doneTk = tk;
                asm volatile("fence.proxy.async;" ::: "memory");
            }
            if (j >= NSTAGE) { mbar_wait(CB + s * 8, cbPh[s]); cbPh[s] ^= 1; }
            const uint32_t st = sb + SMEM_STAGE0 + s * STAGE_BYTES;
            mbar_expect_tx(FULL + s * 8, STAGE_BYTES);
            bulk_g2s(st,              a0Src + (size_t)j * A_UNIT, A_UNIT, FULL + s * 8);
            bulk_g2s(st + A_UNIT,     a1Src + (size_t)j * A_UNIT, A_UNIT, FULL + s * 8);
            bulk_g2s(st + 2 * A_UNIT, bSrc + (size_t)b_unit(j) * B_UNIT, B_UNIT, FULL + s * 8);
        }
    } else if (tid == 32) {
        // ---------------- MMA ISSUER ----------------
        int fullPh[NSTAGE] = {0, 0, 0};
        for (int it = 0; it < NITER; it++) {
            const int s = it % NSTAGE;
            mbar_wait(FULL + s * 8, fullPh[s]); fullPh[s] ^= 1;

            const uint32_t st = sb + SMEM_STAGE0 + s * STAGE_BYTES;
            const uint64_t dA0 = make_desc(st);
            const uint64_t dA1 = make_desc(st + A_UNIT);
            const uint64_t dB  = make_desc(st + 2 * A_UNIT);

            if (it < 32) {
                #pragma unroll
                for (int ks = 0; ks < 4; ks++) {
                    const uint64_t ko = (uint64_t)(ks * 2);   // +32B = 16 bf16 K-elems
                    const uint32_t acc = (it | ks) ? 1u : 0u;
                    mma_f16_ss(tmem +   0, dA0 + ko, dB + ko, acc);   // sub0, N=256
                    mma_f16_ss(tmem + 256, dA1 + ko, dB + ko, acc);   // sub1, N=256
                }
            } else {
                #pragma unroll
                for (int ks = 0; ks < 4; ks++) {
                    const uint64_t ko = (uint64_t)(ks * 2);   // +32B = 32 e4m3 K-elems
                    mma_f8_ss(tmem +   0, dA0 + ko, dB + ko, 1u);
                    mma_f8_ss(tmem + 256, dA1 + ko, dB + ko, 1u);
                }
            }
            tcommit(CB + s * 8);   // releases stage s when MMAs <= it retire
        }
        tcommit(FINAL);
    }

    mbar_wait(FINAL, 0);
    asm volatile("tcgen05.fence::after_thread_sync;" ::: "memory");

    // ---- epilogue: two 128-row halves, TMEM -> swizzled SMEM -> coalesced GMEM
    const int r = wid * 32 + lid;
    uint32_t* epi = (uint32_t*)(smem + SMEM_STAGE0);
    const float scale = 0.022097086912079608f;  // 1/sqrt(2048)
    const float* bch = bias + tn * TN;

    #pragma unroll
    for (int h = 0; h < 2; h++) {
        const uint32_t tbase = tmem + h * 256;
        #pragma unroll
        for (int cb = 0; cb < TN; cb += 32) {
            uint32_t regs[32];
            TLD_32X32B_X32(regs, tbase + cb);
            asm volatile("tcgen05.wait::ld.sync.aligned;" ::: "memory");
            #pragma unroll
            for (int j = 0; j < 32; j++) {
                const int c = cb + j;
                epi[r * TN + (c ^ (r & 31))] = regs[j];
            }
        }
        __syncthreads();

        float* outRow = out + (size_t)(tm * TM + h * TMSUB) * D_OUT + (size_t)tn * TN;
        #pragma unroll 4
        for (int itl = 0; itl < (TMSUB * TN) / 128; itl++) {
            const int i = itl * 128 + tid;
            const int rr = i >> 8;
            const int c = i & 255;
            const float v = __uint_as_float(epi[rr * TN + (c ^ (rr & 31))]);
            outRow[(size_t)rr * D_OUT + c] = v * scale + 0.1f * __ldg(bch + c);
        }
        __syncthreads();
    }

    if (wid == 0)
        asm volatile("tcgen05.dealloc.cta_group::1.sync.aligned.b32 %0, %1;"
                     :: "r"(tmem), "r"(TMEM_COLS));

#else  // ======================= SIMT fp32 fallback =========================
    if (bid < NCONV) return;
    extern __shared__ __align__(16) float fsm[];
    float* ws = fsm;                 // 32 cols x 128 k  (16 KB)
    float* xs = fsm + 32 * 128;      // 128 rows x 132   (66 KB)
    const int tid = threadIdx.x;
    const int g = bid - NCONV;
    const int tn = g & 7, tm = g >> 3;
    const float scale = 0.022097086912079608f;

    for (int sub = 0; sub < 2; sub++) {
        const int rowBase = tm * TM + sub * TMSUB;
        const int row = rowBase + tid;
        for (int nc = 0; nc < TN / 32; nc++) {
            const int cb = tn * TN + nc * 32;
            float acc[32];
            #pragma unroll
            for (int c = 0; c < 32; c++) acc[c] = 0.0f;

            for (int kb = 0; kb < D_IN; kb += 128) {
                __syncthreads();
                for (int i = tid; i < 32 * 128; i += 128)
                    ws[i] = w[(size_t)(cb + (i >> 7)) * D_IN + kb + (i & 127)];
                for (int i = tid; i < 128 * 128; i += 128)
                    xs[(i >> 7) * 132 + (i & 127)] = x[(size_t)(rowBase + (i >> 7)) * D_IN + kb + (i & 127)];
                __syncthreads();

                #pragma unroll 2
                for (int k4 = 0; k4 < 32; k4++) {
                    const float4 xv = *(const float4*)&xs[tid * 132 + k4 * 4];
                    #pragma unroll
                    for (int c = 0; c < 32; c++) {
                        const float4 wv = *(const float4*)&ws[(c << 7) + (k4 << 2)];
                        acc[c] += xv.x * wv.x + xv.y * wv.y + xv.z * wv.z + xv.w * wv.w;
                    }
                }
            }
            #pragma unroll
            for (int c = 0; c < 32; c++)
                out[(size_t)row * D_OUT + cb + c] = acc[c] * scale + 0.1f * bias[cb + c];
        }
    }
#endif
}

// ============================================================================
extern "C" void kernel_launch(void* const* d_in, const int* in_sizes, int n_in,
                              void* d_out, int out_size) {
    const float* x = (const float*)d_in[0];
    const float* w = (const float*)d_in[1];
    const float* b = (const float*)d_in[2];
    float* out = (float*)d_out;

    cudaFuncSetAttribute(fused_kernel, cudaFuncAttributeMaxDynamicSharedMemorySize, SMEM_TOTAL);

    void* fp = nullptr;
    cudaGetSymbolAddress(&fp, g_flags);
    cudaMemsetAsync(fp, 0, 32 * sizeof(int));   // reset readiness flags each call

    fused_kernel<<<NCONV + (D_OUT / TN) * (N_ROWS / TM), 128, SMEM_TOTAL>>>(x, w, b, out);
}